// round 10
// baseline (speedup 1.0000x reference)
#include <cuda_runtime.h>
#include <math.h>

// Problem constants
#define B_     2
#define N_     4096
#define DIM_   1024
#define H_     16
#define D_     64
#define LAT_   1024
#define CTX_   3072
#define SEG_   12
#define CHUNK_ 256
#define BH_    (B_ * H_)
#define M_     (B_ * N_)
#define SCALE_ 0.125f
#define LN_EPS_ 1e-5f

// tf32 GEMM tiling (128 x 64 x 32, 8 warps of 32x32)
#define BM    128
#define BN    64
#define BKK   32
#define KP    36
#define NP2   72
#define ASTG  (BM * KP)
#define BSTG  (BKK * NP2)
#define EPIT  72

// attention smem pitch
#define PQ   68

// epilogue modes
#define EPI_BIAS 0
#define EPI_Q    1
#define EPI_KV   2

// ---------------------------------------------------------------------------
// Scratch
// ---------------------------------------------------------------------------
__device__ float g_qs   [BH_ * N_ * D_];
__device__ float g_lkv  [BH_ * N_ * D_];
__device__ float g_attn [M_ * DIM_];

// ---------------------------------------------------------------------------
// mma + split helpers
// ---------------------------------------------------------------------------
__device__ __forceinline__ void mma_tf32(float (&d)[4],
                                         const unsigned (&a)[4],
                                         const unsigned (&b)[2])
{
    asm volatile(
        "mma.sync.aligned.m16n8k8.row.col.f32.tf32.tf32.f32 "
        "{%0,%1,%2,%3}, {%4,%5,%6,%7}, {%8,%9}, {%0,%1,%2,%3};\n"
        : "+f"(d[0]), "+f"(d[1]), "+f"(d[2]), "+f"(d[3])
        : "r"(a[0]), "r"(a[1]), "r"(a[2]), "r"(a[3]),
          "r"(b[0]), "r"(b[1]));
}

__device__ __forceinline__ void split_hl(float x, unsigned& hi, unsigned& lo)
{
    unsigned xb = __float_as_uint(x);
    hi = xb & 0xFFFFE000u;
    lo = __float_as_uint(x - __uint_as_float(hi));
}

__device__ __forceinline__ void cp16(void* smem_dst, const void* gsrc)
{
    unsigned dst = (unsigned)__cvta_generic_to_shared(smem_dst);
    asm volatile("cp.async.cg.shared.global [%0], [%1], 16;\n"
                 :: "r"(dst), "l"(gsrc));
}

// ---------------------------------------------------------------------------
// 3xTF32 tensor-core GEMM with fused epilogues (unchanged from round 9).
// ---------------------------------------------------------------------------
extern __shared__ float sm_gemm[];

__global__ void __launch_bounds__(256, 3) tf32gemm_kernel(
    const float* __restrict__ A, const float* __restrict__ W,
    const float* __restrict__ bias, float* __restrict__ C,
    int M, int N, int K, int mode,
    const float* __restrict__ ln_g, const float* __restrict__ ln_b)
{
    float* As = sm_gemm;
    float* Bs = sm_gemm + 2 * ASTG;

    int tid  = threadIdx.x;
    int wid  = tid >> 5, lane = tid & 31;
    int wm   = wid >> 1, wn = wid & 1;
    int g    = lane >> 2, t = lane & 3;
    int row0 = blockIdx.y * BM, col0 = blockIdx.x * BN;

    float acc[2][4][4] = {};
    const int NIT = K / BKK;

    auto issue = [&](int it, int stage) {
        int k0 = it * BKK;
#pragma unroll
        for (int i = 0; i < 4; i++) {
            int cidx = tid + i * 256;
            int r = cidx >> 3, c4 = cidx & 7;
            cp16(As + stage * ASTG + r * KP + c4 * 4,
                 A + (size_t)(row0 + r) * K + k0 + c4 * 4);
        }
#pragma unroll
        for (int i = 0; i < 2; i++) {
            int cidx = tid + i * 256;
            int r = cidx >> 4, c4 = cidx & 15;
            cp16(Bs + stage * BSTG + r * NP2 + c4 * 4,
                 W + (size_t)(k0 + r) * N + col0 + c4 * 4);
        }
        asm volatile("cp.async.commit_group;\n");
    };

    issue(0, 0);

    for (int it = 0; it < NIT; it++) {
        int stage = it & 1;
        if (it + 1 < NIT) {
            issue(it + 1, (it + 1) & 1);
            asm volatile("cp.async.wait_group 1;\n");
        } else {
            asm volatile("cp.async.wait_group 0;\n");
        }
        __syncthreads();

        const float* a_s = As + stage * ASTG + (wm * 32) * KP;
        const float* b_s = Bs + stage * BSTG + wn * 32;

#pragma unroll
        for (int ks = 0; ks < 4; ks++) {
            int k0 = ks * 8;
            unsigned ah[2][4], al[2][4];
            unsigned bh[4][2], bl[4][2];
#pragma unroll
            for (int mi = 0; mi < 2; mi++) {
                const float* ap  = a_s + (mi * 16 + g) * KP + k0 + t;
                const float* ap8 = ap + 8 * KP;
                split_hl(ap [0], ah[mi][0], al[mi][0]);
                split_hl(ap8[0], ah[mi][1], al[mi][1]);
                split_hl(ap [4], ah[mi][2], al[mi][2]);
                split_hl(ap8[4], ah[mi][3], al[mi][3]);
            }
#pragma unroll
            for (int ni = 0; ni < 4; ni++) {
                const float* bp = b_s + (k0 + t) * NP2 + ni * 8 + g;
                split_hl(bp[0],       bh[ni][0], bl[ni][0]);
                split_hl(bp[4 * NP2], bh[ni][1], bl[ni][1]);
            }
#pragma unroll
            for (int mi = 0; mi < 2; mi++)
#pragma unroll
                for (int ni = 0; ni < 4; ni++) {
                    mma_tf32(acc[mi][ni], al[mi], bh[ni]);
                    mma_tf32(acc[mi][ni], ah[mi], bl[ni]);
                    mma_tf32(acc[mi][ni], ah[mi], bh[ni]);
                }
        }
        __syncthreads();
    }

    if (mode == EPI_BIAS) {
#pragma unroll
        for (int mi = 0; mi < 2; mi++) {
            int r0 = row0 + wm * 32 + mi * 16 + g;
#pragma unroll
            for (int ni = 0; ni < 4; ni++) {
                int c = col0 + wn * 32 + ni * 8 + 2 * t;
                float bx = bias[c], by = bias[c + 1];
                float2 v0 = {acc[mi][ni][0] + bx, acc[mi][ni][1] + by};
                *(float2*)&C[(size_t)r0 * N + c] = v0;
                float2 v1 = {acc[mi][ni][2] + bx, acc[mi][ni][3] + by};
                *(float2*)&C[(size_t)(r0 + 8) * N + c] = v1;
            }
        }
        return;
    }

    float* Ep = As;

#pragma unroll
    for (int mi = 0; mi < 2; mi++) {
        int r1 = wm * 32 + mi * 16 + g;
#pragma unroll
        for (int ni = 0; ni < 4; ni++) {
            int c = wn * 32 + ni * 8 + 2 * t;
            *(float2*)&Ep[r1 * EPIT + c] =
                make_float2(acc[mi][ni][0], acc[mi][ni][1]);
            *(float2*)&Ep[(r1 + 8) * EPIT + c] =
                make_float2(acc[mi][ni][2], acc[mi][ni][3]);
        }
    }
    __syncthreads();

    int gj = tid & 7;
    int tg = tid >> 3;

    float invd[4];
#pragma unroll
    for (int k = 0; k < 4; k++)
        invd[k] = (float)exp(-0.28782313662425575 * (double)(gj + 8 * k));

    int h  = blockIdx.x;
    int b  = row0 >> 12;
    int nb = row0 & 4095;

    float lg[8], lb[8];
    if (mode == EPI_KV) {
#pragma unroll
        for (int k = 0; k < 8; k++) {
            lg[k] = ln_g[gj + 8 * k];
            lb[k] = ln_b[gj + 8 * k];
        }
    }

#pragma unroll
    for (int i = 0; i < 4; i++) {
        int tk = tg + i * 32;
        int n  = nb + tk;

        float v[8];
#pragma unroll
        for (int k = 0; k < 8; k++) v[k] = Ep[tk * EPIT + gj + 8 * k];

        float out[8];
#pragma unroll
        for (int k = 0; k < 4; k++) {
            float arg = (float)n * invd[k];
            float sn, cs;
            sincosf(arg, &sn, &cs);
            out[k]     = v[k]     * cs - v[k + 4] * sn;
            out[k + 4] = v[k + 4] * cs + v[k]     * sn;
        }

        size_t base = ((size_t)(b * H_ + h) * N_ + n) * D_;
        if (mode == EPI_Q) {
#pragma unroll
            for (int k = 0; k < 8; k++)
                g_qs[base + gj + 8 * k] = out[k] * SCALE_;
        } else {
            float sum = 0.f;
#pragma unroll
            for (int k = 0; k < 8; k++) sum += out[k];
            sum += __shfl_xor_sync(0xffffffffu, sum, 1);
            sum += __shfl_xor_sync(0xffffffffu, sum, 2);
            sum += __shfl_xor_sync(0xffffffffu, sum, 4);
            float mu = sum * (1.0f / 64.0f);
            float ss = 0.f;
#pragma unroll
            for (int k = 0; k < 8; k++) {
                float d = out[k] - mu;
                ss += d * d;
            }
            ss += __shfl_xor_sync(0xffffffffu, ss, 1);
            ss += __shfl_xor_sync(0xffffffffu, ss, 2);
            ss += __shfl_xor_sync(0xffffffffu, ss, 4);
            float rstd = rsqrtf(ss * (1.0f / 64.0f) + LN_EPS_);
#pragma unroll
            for (int k = 0; k < 8; k++)
                g_lkv[base + gj + 8 * k] =
                    (out[k] - mu) * rstd * lg[k] + lb[k];
        }
    }
}

// ---------------------------------------------------------------------------
// Tensorized flash attention v2: warp-private rows.
// CTA = 128 queries, 8 warps x 16 rows; each warp handles ALL 64 keys of a
// tile -> softmax is quad-shuffle-only, P stays warp-local (__syncwarp).
// K tiles double-buffered via cp.async: 2 block barriers per tile.
// smem: Qs[128][PQ] | K0[64][PQ] | K1[64][PQ] | Ps[128][PQ] = 104,448 B.
// ---------------------------------------------------------------------------
extern __shared__ float sm_attn[];

__global__ void __launch_bounds__(256, 2) attn_mma_kernel()
{
    float* Qs  = sm_attn;                    // [128][PQ]
    float* Kb0 = sm_attn + 128 * PQ;         // [64][PQ]
    float* Kb1 = sm_attn + 192 * PQ;         // [64][PQ]
    float* Ps  = sm_attn + 256 * PQ;         // [128][PQ]

    int bh = blockIdx.y;
    int qt = 31 - blockIdx.x;                // latent q-tiles first
    int q0 = qt * 128;
    bool is_lat = (q0 >= CTX_);

    int tid  = threadIdx.x;
    int wid  = tid >> 5, lane = tid & 31;
    int g    = lane >> 2, t = lane & 3;
    int row0 = wid * 16 + g;                 // warp-private rows row0, row0+8

    // ---- load Q tile: 128 rows ----
    {
        const float4* src = (const float4*)(g_qs + ((size_t)bh * N_ + q0) * D_);
#pragma unroll
        for (int i = 0; i < 8; i++) {
            int idx = tid + i * 256;
            int r = idx >> 4, c4 = idx & 15;
            *(float4*)&Qs[r * PQ + c4 * 4] = src[idx];
        }
    }

    float o[8][4] = {};
    float m0 = -3.0e38f, m1 = -3.0e38f, l0 = 0.f, l1 = 0.f;

    int ks0, ntiles;
    if (is_lat) { ks0 = 0;               ntiles = (q0 + 128) >> 6; }
    else        { ks0 = (q0 >> 8) << 8;  ntiles = CHUNK_ / 64; }

    const float* kvb = g_lkv + (size_t)bh * N_ * D_;

    auto issueK = [&](int tt, float* buf) {
        int kt = ks0 + tt * 64;
#pragma unroll
        for (int i = 0; i < 4; i++) {
            int idx = tid + i * 256;
            int r = idx >> 4, c4 = idx & 15;
            cp16(buf + r * PQ + c4 * 4,
                 kvb + (size_t)(kt + r) * D_ + c4 * 4);
        }
        asm volatile("cp.async.commit_group;\n");
    };

    issueK(0, Kb0);

    for (int t0 = 0; t0 < ntiles; t0++) {
        int kt0 = ks0 + t0 * 64;
        float* Kn = (t0 & 1) ? Kb1 : Kb0;

        if (t0 + 1 < ntiles) {
            issueK(t0 + 1, (t0 & 1) ? Kb0 : Kb1);
            asm volatile("cp.async.wait_group 1;\n");
        } else {
            asm volatile("cp.async.wait_group 0;\n");
        }
        __syncthreads();   // K tile t0 visible to all; Q visible (1st iter)

        // ---- S = Q . K^T  (16 rows x 64 keys per warp) ----
        float s[8][4];
#pragma unroll
        for (int ni = 0; ni < 8; ni++)
#pragma unroll
            for (int e = 0; e < 4; e++) s[ni][e] = 0.f;

#pragma unroll
        for (int ks = 0; ks < 8; ks++) {
            int k0 = ks * 8;
            unsigned ah[4], al[4];
            const float* ap  = Qs + row0 * PQ + k0 + t;
            const float* ap8 = ap + 8 * PQ;
            split_hl(ap [0], ah[0], al[0]);
            split_hl(ap8[0], ah[1], al[1]);
            split_hl(ap [4], ah[2], al[2]);
            split_hl(ap8[4], ah[3], al[3]);
#pragma unroll
            for (int ni = 0; ni < 8; ni++) {
                unsigned bh2[2], bl2[2];
                const float* bp = Kn + (ni * 8 + g) * PQ + k0 + t;
                split_hl(bp[0], bh2[0], bl2[0]);
                split_hl(bp[4], bh2[1], bl2[1]);
                mma_tf32(s[ni], al, bh2);
                mma_tf32(s[ni], ah, bl2);
                mma_tf32(s[ni], ah, bh2);
            }
        }

        // ---- causal mask among latent keys (only near the diagonal) ----
        if (is_lat && kt0 + 63 > q0) {
#pragma unroll
            for (int ni = 0; ni < 8; ni++) {
                int col = ni * 8 + 2 * t;
                if (kt0 + col     > q0 + row0)     s[ni][0] = -3.0e38f;
                if (kt0 + col + 1 > q0 + row0)     s[ni][1] = -3.0e38f;
                if (kt0 + col     > q0 + row0 + 8) s[ni][2] = -3.0e38f;
                if (kt0 + col + 1 > q0 + row0 + 8) s[ni][3] = -3.0e38f;
            }
        }

        // ---- softmax: quad-only reductions ----
        float mx0 = -3.0e38f, mx1 = -3.0e38f;
#pragma unroll
        for (int ni = 0; ni < 8; ni++) {
            mx0 = fmaxf(mx0, fmaxf(s[ni][0], s[ni][1]));
            mx1 = fmaxf(mx1, fmaxf(s[ni][2], s[ni][3]));
        }
        mx0 = fmaxf(mx0, __shfl_xor_sync(0xffffffffu, mx0, 1));
        mx0 = fmaxf(mx0, __shfl_xor_sync(0xffffffffu, mx0, 2));
        mx1 = fmaxf(mx1, __shfl_xor_sync(0xffffffffu, mx1, 1));
        mx1 = fmaxf(mx1, __shfl_xor_sync(0xffffffffu, mx1, 2));

        float mn0 = fmaxf(m0, mx0), mn1 = fmaxf(m1, mx1);
        float corr0 = __expf(m0 - mn0), corr1 = __expf(m1 - mn1);
        m0 = mn0; m1 = mn1;

        float rs0 = 0.f, rs1 = 0.f;
#pragma unroll
        for (int ni = 0; ni < 8; ni++) {
            int col = ni * 8 + 2 * t;
            float p0 = __expf(s[ni][0] - m0);
            float p1 = __expf(s[ni][1] - m0);
            float p2 = __expf(s[ni][2] - m1);
            float p3 = __expf(s[ni][3] - m1);
            rs0 += p0 + p1;
            rs1 += p2 + p3;
            *(float2*)&Ps[row0 * PQ + col]       = make_float2(p0, p1);
            *(float2*)&Ps[(row0 + 8) * PQ + col] = make_float2(p2, p3);
        }
        rs0 += __shfl_xor_sync(0xffffffffu, rs0, 1);
        rs0 += __shfl_xor_sync(0xffffffffu, rs0, 2);
        rs1 += __shfl_xor_sync(0xffffffffu, rs1, 1);
        rs1 += __shfl_xor_sync(0xffffffffu, rs1, 2);
        l0 = l0 * corr0 + rs0;
        l1 = l1 * corr1 + rs1;

#pragma unroll
        for (int ni = 0; ni < 8; ni++) {
            o[ni][0] *= corr0; o[ni][1] *= corr0;
            o[ni][2] *= corr1; o[ni][3] *= corr1;
        }

        __syncwarp();      // P rows are warp-private: warp fence suffices

        // ---- O += P . K  (16 rows x 64 dims per warp) ----
#pragma unroll
        for (int ks = 0; ks < 8; ks++) {
            int k0 = ks * 8;
            unsigned ah[4], al[4];
            const float* ap  = Ps + row0 * PQ + k0 + t;
            const float* ap8 = ap + 8 * PQ;
            split_hl(ap [0], ah[0], al[0]);
            split_hl(ap8[0], ah[1], al[1]);
            split_hl(ap [4], ah[2], al[2]);
            split_hl(ap8[4], ah[3], al[3]);
#pragma unroll
            for (int ni = 0; ni < 8; ni++) {
                unsigned bh2[2], bl2[2];
                const float* bp = Kn + (k0 + t) * PQ + ni * 8 + g;
                split_hl(bp[0],      bh2[0], bl2[0]);
                split_hl(bp[4 * PQ], bh2[1], bl2[1]);
                mma_tf32(o[ni], al, bh2);
                mma_tf32(o[ni], ah, bl2);
                mma_tf32(o[ni], ah, bh2);
            }
        }

        if (t0 + 1 < ntiles)
            __syncthreads();   // all warps done with Kn before it is reissued
    }

    // ---- epilogue ----
    float inv0 = 1.0f / l0, inv1 = 1.0f / l1;
    int b = bh / H_, h = bh % H_;
    int tok0 = q0 + row0;
#pragma unroll
    for (int ni = 0; ni < 8; ni++) {
        int col = h * D_ + ni * 8 + 2 * t;
        float2 v0 = make_float2(o[ni][0] * inv0, o[ni][1] * inv0);
        *(float2*)&g_attn[((size_t)(b * N_ + tok0)) * DIM_ + col] = v0;
        float2 v1 = make_float2(o[ni][2] * inv1, o[ni][3] * inv1);
        *(float2*)&g_attn[((size_t)(b * N_ + tok0 + 8)) * DIM_ + col] = v1;
    }
}

// ---------------------------------------------------------------------------
// Launch
// ---------------------------------------------------------------------------
extern "C" void kernel_launch(void* const* d_in, const int* in_sizes, int n_in,
                              void* d_out, int out_size)
{
    const float* x   = (const float*)d_in[0];
    const float* Wq  = (const float*)d_in[1];
    const float* Wkv = (const float*)d_in[2];
    const float* Wo  = (const float*)d_in[3];
    const float* bo  = (const float*)d_in[4];
    const float* lng = (const float*)d_in[5];
    const float* lnb = (const float*)d_in[6];
    float* out = (float*)d_out;

    float* attn;
    cudaGetSymbolAddress((void**)&attn, g_attn);

    int attn_smem = 384 * PQ * (int)sizeof(float);           // 104,448 B
    int gemm_smem = 2 * (ASTG + BSTG) * (int)sizeof(float);  // 55,296 B

    static int attr_set = 0;
    if (!attr_set) {
        cudaFuncSetAttribute(attn_mma_kernel,
                             cudaFuncAttributeMaxDynamicSharedMemorySize,
                             attn_smem);
        cudaFuncSetAttribute(tf32gemm_kernel,
                             cudaFuncAttributeMaxDynamicSharedMemorySize,
                             gemm_smem);
        attr_set = 1;
    }

    dim3 gemm_grid(DIM_ / BN, M_ / BM);   // (16, 64)

    tf32gemm_kernel<<<gemm_grid, 256, gemm_smem>>>(
        x, Wq, nullptr, nullptr, M_, DIM_, DIM_, EPI_Q, nullptr, nullptr);
    tf32gemm_kernel<<<gemm_grid, 256, gemm_smem>>>(
        x, Wkv, nullptr, nullptr, M_, DIM_, DIM_, EPI_KV, lng, lnb);
    attn_mma_kernel<<<dim3(32, BH_), 256, attn_smem>>>();
    tf32gemm_kernel<<<gemm_grid, 256, gemm_smem>>>(
        attn, Wo, bo, out, M_, DIM_, DIM_, EPI_BIAS, nullptr, nullptr);
}

// round 16
// speedup vs baseline: 1.0525x; 1.0525x over previous
#include <cuda_runtime.h>
#include <math.h>

// Problem constants
#define B_     2
#define N_     4096
#define DIM_   1024
#define H_     16
#define D_     64
#define LAT_   1024
#define CTX_   3072
#define SEG_   12
#define CHUNK_ 256
#define BH_    (B_ * H_)
#define M_     (B_ * N_)
#define SCALE_ 0.125f
#define LN_EPS_ 1e-5f

// tf32 GEMM tiling (128 x 64 x 32, 8 warps of 32x32)
#define BM    128
#define BN    64
#define BKK   32
#define KP    36
#define NP2   72
#define ASTG  (BM * KP)
#define BSTG  (BKK * NP2)
#define EPIT  72

// attention smem pitch
#define PQ   68

// epilogue modes
#define EPI_BIAS 0
#define EPI_Q    1
#define EPI_KV   2
#define EPI_QKV  3   // fused launch: blockIdx.x 0-15 -> Q, 16-31 -> KV

// ---------------------------------------------------------------------------
// Scratch
// ---------------------------------------------------------------------------
__device__ float g_qs   [BH_ * N_ * D_];
__device__ float g_lkv  [BH_ * N_ * D_];
__device__ float g_attn [M_ * DIM_];

// ---------------------------------------------------------------------------
// mma + split helpers (pure-C bit manipulation — the proven path)
// ---------------------------------------------------------------------------
__device__ __forceinline__ void mma_tf32(float (&d)[4],
                                         const unsigned (&a)[4],
                                         const unsigned (&b)[2])
{
    asm volatile(
        "mma.sync.aligned.m16n8k8.row.col.f32.tf32.tf32.f32 "
        "{%0,%1,%2,%3}, {%4,%5,%6,%7}, {%8,%9}, {%0,%1,%2,%3};\n"
        : "+f"(d[0]), "+f"(d[1]), "+f"(d[2]), "+f"(d[3])
        : "r"(a[0]), "r"(a[1]), "r"(a[2]), "r"(a[3]),
          "r"(b[0]), "r"(b[1]));
}

__device__ __forceinline__ void split_hl(float x, unsigned& hi, unsigned& lo)
{
    unsigned xb = __float_as_uint(x);
    hi = xb & 0xFFFFE000u;
    lo = __float_as_uint(x - __uint_as_float(hi));
}

__device__ __forceinline__ void cp16(void* smem_dst, const void* gsrc)
{
    unsigned dst = (unsigned)__cvta_generic_to_shared(smem_dst);
    asm volatile("cp.async.cg.shared.global [%0], [%1], 16;\n"
                 :: "r"(dst), "l"(gsrc));
}

// ---------------------------------------------------------------------------
// 3xTF32 tensor-core GEMM with fused epilogues. Round-9 math verbatim;
// EPI_QKV routes blocks 0-15 -> x.Wq (RoPE*scale) and 16-31 -> x.Wkv
// (RoPE+LN), fusing both projections into one launch.
// ---------------------------------------------------------------------------
extern __shared__ float sm_gemm[];

__global__ void __launch_bounds__(256, 3) tf32gemm_kernel(
    const float* __restrict__ A, const float* __restrict__ W0,
    const float* __restrict__ W1,
    const float* __restrict__ bias, float* __restrict__ C,
    int M, int N, int K, int mode,
    const float* __restrict__ ln_g, const float* __restrict__ ln_b)
{
    float* As = sm_gemm;
    float* Bs = sm_gemm + 2 * ASTG;

    int tid  = threadIdx.x;
    int wid  = tid >> 5, lane = tid & 31;
    int wm   = wid >> 1, wn = wid & 1;
    int g    = lane >> 2, t = lane & 3;
    int row0 = blockIdx.y * BM;

    const float* W;
    int col0, emode;
    if (mode == EPI_QKV) {
        bool iskv = (blockIdx.x >= 16);
        W     = iskv ? W1 : W0;
        col0  = (blockIdx.x & 15) * BN;
        emode = iskv ? EPI_KV : EPI_Q;
    } else {
        W     = W0;
        col0  = blockIdx.x * BN;
        emode = EPI_BIAS;
    }

    float acc[2][4][4] = {};
    const int NIT = K / BKK;

    auto issue = [&](int it, int stage) {
        int k0 = it * BKK;
#pragma unroll
        for (int i = 0; i < 4; i++) {
            int cidx = tid + i * 256;
            int r = cidx >> 3, c4 = cidx & 7;
            cp16(As + stage * ASTG + r * KP + c4 * 4,
                 A + (size_t)(row0 + r) * K + k0 + c4 * 4);
        }
#pragma unroll
        for (int i = 0; i < 2; i++) {
            int cidx = tid + i * 256;
            int r = cidx >> 4, c4 = cidx & 15;
            cp16(Bs + stage * BSTG + r * NP2 + c4 * 4,
                 W + (size_t)(k0 + r) * N + col0 + c4 * 4);
        }
        asm volatile("cp.async.commit_group;\n");
    };

    issue(0, 0);

    for (int it = 0; it < NIT; it++) {
        int stage = it & 1;
        if (it + 1 < NIT) {
            issue(it + 1, (it + 1) & 1);
            asm volatile("cp.async.wait_group 1;\n");
        } else {
            asm volatile("cp.async.wait_group 0;\n");
        }
        __syncthreads();

        const float* a_s = As + stage * ASTG + (wm * 32) * KP;
        const float* b_s = Bs + stage * BSTG + wn * 32;

#pragma unroll
        for (int ks = 0; ks < 4; ks++) {
            int k0 = ks * 8;
            unsigned ah[2][4], al[2][4];
            unsigned bh[4][2], bl[4][2];
#pragma unroll
            for (int mi = 0; mi < 2; mi++) {
                const float* ap  = a_s + (mi * 16 + g) * KP + k0 + t;
                const float* ap8 = ap + 8 * KP;
                split_hl(ap [0], ah[mi][0], al[mi][0]);
                split_hl(ap8[0], ah[mi][1], al[mi][1]);
                split_hl(ap [4], ah[mi][2], al[mi][2]);
                split_hl(ap8[4], ah[mi][3], al[mi][3]);
            }
#pragma unroll
            for (int ni = 0; ni < 4; ni++) {
                const float* bp = b_s + (k0 + t) * NP2 + ni * 8 + g;
                split_hl(bp[0],       bh[ni][0], bl[ni][0]);
                split_hl(bp[4 * NP2], bh[ni][1], bl[ni][1]);
            }
#pragma unroll
            for (int mi = 0; mi < 2; mi++)
#pragma unroll
                for (int ni = 0; ni < 4; ni++) {
                    mma_tf32(acc[mi][ni], al[mi], bh[ni]);
                    mma_tf32(acc[mi][ni], ah[mi], bl[ni]);
                    mma_tf32(acc[mi][ni], ah[mi], bh[ni]);
                }
        }
        __syncthreads();
    }

    if (emode == EPI_BIAS) {
#pragma unroll
        for (int mi = 0; mi < 2; mi++) {
            int r0 = row0 + wm * 32 + mi * 16 + g;
#pragma unroll
            for (int ni = 0; ni < 4; ni++) {
                int c = col0 + wn * 32 + ni * 8 + 2 * t;
                float bx = bias[c], by = bias[c + 1];
                float2 v0 = {acc[mi][ni][0] + bx, acc[mi][ni][1] + by};
                *(float2*)&C[(size_t)r0 * N + c] = v0;
                float2 v1 = {acc[mi][ni][2] + bx, acc[mi][ni][3] + by};
                *(float2*)&C[(size_t)(r0 + 8) * N + c] = v1;
            }
        }
        return;
    }

    // ---- fused RoPE(/LN) epilogue: tile = 128 tokens x one head ----
    float* Ep = As;

#pragma unroll
    for (int mi = 0; mi < 2; mi++) {
        int r1 = wm * 32 + mi * 16 + g;
#pragma unroll
        for (int ni = 0; ni < 4; ni++) {
            int c = wn * 32 + ni * 8 + 2 * t;
            *(float2*)&Ep[r1 * EPIT + c] =
                make_float2(acc[mi][ni][0], acc[mi][ni][1]);
            *(float2*)&Ep[(r1 + 8) * EPIT + c] =
                make_float2(acc[mi][ni][2], acc[mi][ni][3]);
        }
    }
    __syncthreads();

    int gj = tid & 7;
    int tg = tid >> 3;

    float invd[4];
#pragma unroll
    for (int k = 0; k < 4; k++)
        invd[k] = (float)exp(-0.28782313662425575 * (double)(gj + 8 * k));

    int h  = blockIdx.x & 15;
    int b  = row0 >> 12;
    int nb = row0 & 4095;

    float lg[8], lb[8];
    if (emode == EPI_KV) {
#pragma unroll
        for (int k = 0; k < 8; k++) {
            lg[k] = ln_g[gj + 8 * k];
            lb[k] = ln_b[gj + 8 * k];
        }
    }

#pragma unroll
    for (int i = 0; i < 4; i++) {
        int tk = tg + i * 32;
        int n  = nb + tk;

        float v[8];
#pragma unroll
        for (int k = 0; k < 8; k++) v[k] = Ep[tk * EPIT + gj + 8 * k];

        float out[8];
#pragma unroll
        for (int k = 0; k < 4; k++) {
            float arg = (float)n * invd[k];
            float sn, cs;
            sincosf(arg, &sn, &cs);
            out[k]     = v[k]     * cs - v[k + 4] * sn;
            out[k + 4] = v[k + 4] * cs + v[k]     * sn;
        }

        size_t base = ((size_t)(b * H_ + h) * N_ + n) * D_;
        if (emode == EPI_Q) {
#pragma unroll
            for (int k = 0; k < 8; k++)
                g_qs[base + gj + 8 * k] = out[k] * SCALE_;
        } else {
            float sum = 0.f;
#pragma unroll
            for (int k = 0; k < 8; k++) sum += out[k];
            sum += __shfl_xor_sync(0xffffffffu, sum, 1);
            sum += __shfl_xor_sync(0xffffffffu, sum, 2);
            sum += __shfl_xor_sync(0xffffffffu, sum, 4);
            float mu = sum * (1.0f / 64.0f);
            float ss = 0.f;
#pragma unroll
            for (int k = 0; k < 8; k++) {
                float d = out[k] - mu;
                ss += d * d;
            }
            ss += __shfl_xor_sync(0xffffffffu, ss, 1);
            ss += __shfl_xor_sync(0xffffffffu, ss, 2);
            ss += __shfl_xor_sync(0xffffffffu, ss, 4);
            float rstd = rsqrtf(ss * (1.0f / 64.0f) + LN_EPS_);
#pragma unroll
            for (int k = 0; k < 8; k++)
                g_lkv[base + gj + 8 * k] =
                    (out[k] - mu) * rstd * lg[k] + lb[k];
        }
    }
}

// ---------------------------------------------------------------------------
// Tensorized flash attention (round-9 math, 3x truncation everywhere) with
// cp.async double-buffered K tiles. FIXED epilogue: col includes wn*32
// (the transcription bug that broke rounds 11-15).
// smem: Qs[64] | Kb0[64] | Kb1[64] | Ps[64] (PQ pitch) + redm/reds.
// ---------------------------------------------------------------------------
extern __shared__ float sm_attn[];

__global__ void __launch_bounds__(256, 3) attn_mma_kernel()
{
    float* Qs   = sm_attn;
    float* Kb0  = sm_attn + 64 * PQ;
    float* Kb1  = sm_attn + 128 * PQ;
    float* Ps   = sm_attn + 192 * PQ;
    float* redm = sm_attn + 256 * PQ;          // [2][64]
    float* reds = redm + 128;                  // [2][64]

    int bh = blockIdx.y;
    int qt = 63 - blockIdx.x;
    int q0 = qt * 64;
    bool is_lat = (q0 >= CTX_);

    int tid  = threadIdx.x;
    int wid  = tid >> 5, lane = tid & 31;
    int wm   = wid >> 1, wn = wid & 1;
    int g    = lane >> 2, t = lane & 3;

    int row0 = wm * 16 + g;
    int lrow = tid >> 4, lc4 = tid & 15;

    // ---- load Q tile ----
    {
        const float4* src = (const float4*)(g_qs + ((size_t)bh * N_ + q0) * D_);
#pragma unroll
        for (int it = 0; it < 4; it++) {
            int row = lrow + it * 16;
            *(float4*)&Qs[row * PQ + lc4 * 4] = src[row * 16 + lc4];
        }
    }

    float s[4][4];
    float o[4][4] = {};
    float m0 = -3.0e38f, m1 = -3.0e38f, l0 = 0.f, l1 = 0.f;

    int ks0, ntiles;
    if (is_lat) { ks0 = 0;               ntiles = qt + 1; }
    else        { ks0 = (q0 >> 8) << 8;  ntiles = CHUNK_ / 64; }

    const float* kvb = g_lkv + (size_t)bh * N_ * D_;

    auto issueK = [&](int tt, float* buf) {
        int kt = ks0 + tt * 64;
#pragma unroll
        for (int i = 0; i < 4; i++) {
            int idx = tid + i * 256;
            int r = idx >> 4, c4 = idx & 15;
            cp16(buf + r * PQ + c4 * 4,
                 kvb + (size_t)(kt + r) * D_ + c4 * 4);
        }
        asm volatile("cp.async.commit_group;\n");
    };

    issueK(0, Kb0);

    for (int t0 = 0; t0 < ntiles; t0++) {
        int kt0 = ks0 + t0 * 64;
        float* Kn = (t0 & 1) ? Kb1 : Kb0;

        if (t0 + 1 < ntiles) {
            // prefetch next tile into the alternate buffer; the end-of-
            // iteration barrier of t0-1 guarantees all reads of it are done.
            issueK(t0 + 1, (t0 & 1) ? Kb0 : Kb1);
            asm volatile("cp.async.wait_group 1;\n");
        } else {
            asm volatile("cp.async.wait_group 0;\n");
        }
        __syncthreads();   // Kn visible to all warps (+ Qs on first iter)

        // ---- S = Q . K^T (3x) : B[k=d][n=key] = Kn[key][d] ----
#pragma unroll
        for (int ni = 0; ni < 4; ni++)
#pragma unroll
            for (int e = 0; e < 4; e++) s[ni][e] = 0.f;

#pragma unroll
        for (int ks = 0; ks < 8; ks++) {
            int k0 = ks * 8;
            unsigned ah[4], al[4], bh2[4][2], bl2[4][2];
            const float* ap  = Qs + row0 * PQ + k0 + t;
            const float* ap8 = ap + 8 * PQ;
            split_hl(ap [0], ah[0], al[0]);
            split_hl(ap8[0], ah[1], al[1]);
            split_hl(ap [4], ah[2], al[2]);
            split_hl(ap8[4], ah[3], al[3]);
#pragma unroll
            for (int ni = 0; ni < 4; ni++) {
                const float* bp = Kn + (wn * 32 + ni * 8 + g) * PQ + k0 + t;
                split_hl(bp[0], bh2[ni][0], bl2[ni][0]);
                split_hl(bp[4], bh2[ni][1], bl2[ni][1]);
            }
#pragma unroll
            for (int ni = 0; ni < 4; ni++) {
                mma_tf32(s[ni], al, bh2[ni]);
                mma_tf32(s[ni], ah, bl2[ni]);
                mma_tf32(s[ni], ah, bh2[ni]);
            }
        }

        if (is_lat && kt0 >= CTX_) {
#pragma unroll
            for (int ni = 0; ni < 4; ni++) {
                int col = wn * 32 + ni * 8 + 2 * t;
                if (kt0 + col     > q0 + row0)     s[ni][0] = -3.0e38f;
                if (kt0 + col + 1 > q0 + row0)     s[ni][1] = -3.0e38f;
                if (kt0 + col     > q0 + row0 + 8) s[ni][2] = -3.0e38f;
                if (kt0 + col + 1 > q0 + row0 + 8) s[ni][3] = -3.0e38f;
            }
        }

        float mx0 = -3.0e38f, mx1 = -3.0e38f;
#pragma unroll
        for (int ni = 0; ni < 4; ni++) {
            mx0 = fmaxf(mx0, fmaxf(s[ni][0], s[ni][1]));
            mx1 = fmaxf(mx1, fmaxf(s[ni][2], s[ni][3]));
        }
        mx0 = fmaxf(mx0, __shfl_xor_sync(0xffffffffu, mx0, 1));
        mx0 = fmaxf(mx0, __shfl_xor_sync(0xffffffffu, mx0, 2));
        mx1 = fmaxf(mx1, __shfl_xor_sync(0xffffffffu, mx1, 1));
        mx1 = fmaxf(mx1, __shfl_xor_sync(0xffffffffu, mx1, 2));
        if (t == 0) {
            redm[wn * 64 + row0]     = mx0;
            redm[wn * 64 + row0 + 8] = mx1;
        }
        __syncthreads();

        float gm0 = fmaxf(redm[row0],     redm[64 + row0]);
        float gm1 = fmaxf(redm[row0 + 8], redm[64 + row0 + 8]);
        float mn0 = fmaxf(m0, gm0), mn1 = fmaxf(m1, gm1);
        float corr0 = __expf(m0 - mn0), corr1 = __expf(m1 - mn1);
        m0 = mn0; m1 = mn1;

        float rs0 = 0.f, rs1 = 0.f;
#pragma unroll
        for (int ni = 0; ni < 4; ni++) {
            int col = wn * 32 + ni * 8 + 2 * t;
            float p0 = __expf(s[ni][0] - m0);
            float p1 = __expf(s[ni][1] - m0);
            float p2 = __expf(s[ni][2] - m1);
            float p3 = __expf(s[ni][3] - m1);
            rs0 += p0 + p1;
            rs1 += p2 + p3;
            *(float2*)&Ps[row0 * PQ + col]       = make_float2(p0, p1);
            *(float2*)&Ps[(row0 + 8) * PQ + col] = make_float2(p2, p3);
        }
        rs0 += __shfl_xor_sync(0xffffffffu, rs0, 1);
        rs0 += __shfl_xor_sync(0xffffffffu, rs0, 2);
        rs1 += __shfl_xor_sync(0xffffffffu, rs1, 1);
        rs1 += __shfl_xor_sync(0xffffffffu, rs1, 2);
        if (t == 0) {
            reds[wn * 64 + row0]     = rs0;
            reds[wn * 64 + row0 + 8] = rs1;
        }

#pragma unroll
        for (int ni = 0; ni < 4; ni++) {
            o[ni][0] *= corr0; o[ni][1] *= corr0;
            o[ni][2] *= corr1; o[ni][3] *= corr1;
        }
        __syncthreads();

        l0 = l0 * corr0 + reds[row0]     + reds[64 + row0];
        l1 = l1 * corr1 + reds[row0 + 8] + reds[64 + row0 + 8];

        // ---- O += P . K (3x) : B[k=key][n=d] = Kn[key][d] ----
#pragma unroll
        for (int ks = 0; ks < 8; ks++) {
            int k0 = ks * 8;
            unsigned ah[4], al[4], bh2[4][2], bl2[4][2];
            const float* ap  = Ps + row0 * PQ + k0 + t;
            const float* ap8 = ap + 8 * PQ;
            split_hl(ap [0], ah[0], al[0]);
            split_hl(ap8[0], ah[1], al[1]);
            split_hl(ap [4], ah[2], al[2]);
            split_hl(ap8[4], ah[3], al[3]);
#pragma unroll
            for (int ni = 0; ni < 4; ni++) {
                const float* bp = Kn + (k0 + t) * PQ + wn * 32 + ni * 8 + g;
                split_hl(bp[0],      bh2[ni][0], bl2[ni][0]);
                split_hl(bp[4 * PQ], bh2[ni][1], bl2[ni][1]);
            }
#pragma unroll
            for (int ni = 0; ni < 4; ni++) {
                mma_tf32(o[ni], al, bh2[ni]);
                mma_tf32(o[ni], ah, bl2[ni]);
                mma_tf32(o[ni], ah, bh2[ni]);
            }
        }

        __syncthreads();   // all warps done with Kn before it is re-filled
    }

    // ---- epilogue (FIXED: wn*32 restored) ----
    float inv0 = 1.0f / l0, inv1 = 1.0f / l1;
    int b = bh / H_, h = bh % H_;
    int tok0 = q0 + row0;
#pragma unroll
    for (int ni = 0; ni < 4; ni++) {
        int col = h * D_ + wn * 32 + ni * 8 + 2 * t;
        float2 v0 = make_float2(o[ni][0] * inv0, o[ni][1] * inv0);
        *(float2*)&g_attn[((size_t)(b * N_ + tok0)) * DIM_ + col] = v0;
        float2 v1 = make_float2(o[ni][2] * inv1, o[ni][3] * inv1);
        *(float2*)&g_attn[((size_t)(b * N_ + tok0 + 8)) * DIM_ + col] = v1;
    }
}

// ---------------------------------------------------------------------------
// Launch: fused QKV projection (one 32x64 launch), attention, output GEMM.
// ---------------------------------------------------------------------------
extern "C" void kernel_launch(void* const* d_in, const int* in_sizes, int n_in,
                              void* d_out, int out_size)
{
    const float* x   = (const float*)d_in[0];
    const float* Wq  = (const float*)d_in[1];
    const float* Wkv = (const float*)d_in[2];
    const float* Wo  = (const float*)d_in[3];
    const float* bo  = (const float*)d_in[4];
    const float* lng = (const float*)d_in[5];
    const float* lnb = (const float*)d_in[6];
    float* out = (float*)d_out;

    float* attn;
    cudaGetSymbolAddress((void**)&attn, g_attn);

    int attn_smem = (256 * PQ + 256) * (int)sizeof(float);   // 70,656 B
    int gemm_smem = 2 * (ASTG + BSTG) * (int)sizeof(float);  // 55,296 B

    static int attr_set = 0;
    if (!attr_set) {
        cudaFuncSetAttribute(attn_mma_kernel,
                             cudaFuncAttributeMaxDynamicSharedMemorySize,
                             attn_smem);
        cudaFuncSetAttribute(tf32gemm_kernel,
                             cudaFuncAttributeMaxDynamicSharedMemorySize,
                             gemm_smem);
        attr_set = 1;
    }

    // fused Q + KV projections: blocks 0-15 -> Q heads, 16-31 -> KV heads
    tf32gemm_kernel<<<dim3(32, M_ / BM), 256, gemm_smem>>>(
        x, Wq, Wkv, nullptr, nullptr, M_, DIM_, DIM_, EPI_QKV, lng, lnb);
    attn_mma_kernel<<<dim3(64, BH_), 256, attn_smem>>>();
    tf32gemm_kernel<<<dim3(16, M_ / BM), 256, gemm_smem>>>(
        attn, Wo, nullptr, bo, out, M_, DIM_, DIM_, EPI_BIAS, nullptr, nullptr);
}